// round 4
// baseline (speedup 1.0000x reference)
#include <cuda_runtime.h>

#define DD   256
#define E2   512
#define NT   128
#define NF   128
#define NBN  16
#define SROW 516
#define EPS  1e-5f

typedef unsigned long long u64;

// ---------------- packed f32x2 helpers (Blackwell 2xFP32) ------------------
__device__ __forceinline__ u64 add2(u64 a, u64 b) {
    u64 d; asm("add.rn.f32x2 %0,%1,%2;" : "=l"(d) : "l"(a), "l"(b)); return d;
}
__device__ __forceinline__ u64 fma2(u64 a, u64 b, u64 c) {
    u64 d; asm("fma.rn.f32x2 %0,%1,%2,%3;" : "=l"(d) : "l"(a), "l"(b), "l"(c)); return d;
}
__device__ __forceinline__ u64 relu2(u64 a) {
    u64 d;
    asm("{\n\t.reg .f32 l,h;\n\tmov.b64 {l,h}, %1;\n\t"
        "max.f32 l, l, 0f00000000;\n\tmax.f32 h, h, 0f00000000;\n\t"
        "mov.b64 %0, {l,h};\n\t}" : "=l"(d) : "l"(a));
    return d;
}
__device__ __forceinline__ float sum2(u64 a) {
    float l, h; asm("mov.b64 {%0,%1}, %2;" : "=f"(l), "=f"(h) : "l"(a)); return l + h;
}
__device__ __forceinline__ u64 pack2(float v) {
    u64 d; asm("mov.b64 %0, {%1,%1};" : "=l"(d) : "f"(v)); return d;
}

// ---------------- scratch (device globals; no allocation allowed) ----------
__device__ float g_cx[NBN * DD];
__device__ float g_ct[NT * DD];
__device__ float g_cf[NF * DD];
__device__ float g_qx[NBN];
__device__ float g_qt[NT];
__device__ float g_qf[NF];
__device__ float g_dxt[NBN * NT];
__device__ float g_dxf[NBN * NF];
__device__ float g_dtf[NT * NF];
__device__ float g_ux[NBN * E2];
__device__ float g_ut[NT * E2];
__device__ float g_uf[NF * E2];
__device__ float g_c[E2];

// ---------------- P1: center each embedding row, store centered + sq-norm --
__global__ void k_center(const float* __restrict__ x,
                         const float* __restrict__ t_emb,
                         const float* __restrict__ f_emb) {
    __shared__ float red[8];
    __shared__ float s_mu;
    int r = blockIdx.x;
    const float* src;
    float* dst;
    float* q;
    if (r < 16)       { src = x + r * DD;            dst = g_cx + r * DD;        q = g_qx + r; }
    else if (r < 144) { int i = r - 16;  src = t_emb + i * DD; dst = g_ct + i * DD; q = g_qt + i; }
    else              { int i = r - 144; src = f_emb + i * DD; dst = g_cf + i * DD; q = g_qf + i; }

    int tid = threadIdx.x;
    float v = src[tid];

    float s = v;
    #pragma unroll
    for (int o = 16; o; o >>= 1) s += __shfl_xor_sync(0xffffffffu, s, o);
    if ((tid & 31) == 0) red[tid >> 5] = s;
    __syncthreads();
    if (tid == 0) {
        float tot = 0.f;
        #pragma unroll
        for (int i = 0; i < 8; i++) tot += red[i];
        s_mu = tot * (1.0f / DD);
    }
    __syncthreads();

    float c = v - s_mu;
    dst[tid] = c;

    s = c * c;
    #pragma unroll
    for (int o = 16; o; o >>= 1) s += __shfl_xor_sync(0xffffffffu, s, o);
    __syncthreads();
    if ((tid & 31) == 0) red[tid >> 5] = s;
    __syncthreads();
    if (tid == 0) {
        float tot = 0.f;
        #pragma unroll
        for (int i = 0; i < 8; i++) tot += red[i];
        *q = tot;
    }
}

// ---------------- P2: pairwise dot products (one warp per dot) -------------
__global__ void k_dots() {
    int w    = (blockIdx.x * blockDim.x + threadIdx.x) >> 5;
    int lane = threadIdx.x & 31;
    const float *a, *b;
    float* dst;
    if (w < 2048) {
        int i = w >> 7, j = w & 127;
        a = g_cx + i * DD; b = g_ct + j * DD; dst = g_dxt + w;
    } else if (w < 4096) {
        int w2 = w - 2048;
        int i = w2 >> 7, j = w2 & 127;
        a = g_cx + i * DD; b = g_cf + j * DD; dst = g_dxf + w2;
    } else {
        int w3 = w - 4096;
        a = g_ct + (w3 >> 7) * DD; b = g_cf + (w3 & 127) * DD; dst = g_dtf + w3;
    }
    const float4* a4 = (const float4*)a;
    const float4* b4 = (const float4*)b;
    float s = 0.f;
    #pragma unroll
    for (int j = 0; j < 2; j++) {
        float4 av = a4[lane * 2 + j];
        float4 bv = b4[lane * 2 + j];
        s += av.x * bv.x + av.y * bv.y + av.z * bv.z + av.w * bv.w;
    }
    #pragma unroll
    for (int o = 16; o; o >>= 1) s += __shfl_xor_sync(0xffffffffu, s, o);
    if (lane == 0) *dst = s;
}

// ---------------- P3: 4 rows/block through W1 (one W1 stream per block) ----
__global__ void k_project(const float* __restrict__ ln_g,
                          const float* __restrict__ ln_b,
                          const float* __restrict__ W1,
                          const float* __restrict__ b1) {
    __shared__ float4 cg[DD];   // [k] -> (row0..row3)
    int r0 = blockIdx.x * 4;
    int e = threadIdx.x;        // 512 threads

    if (e < DD) {
        float g = ln_g[e];
        float4 v;
        float* vp = (float*)&v;
        #pragma unroll
        for (int j = 0; j < 4; j++) {
            int r = r0 + j;
            float c;
            if (r < 16)        c = g_cx[r * DD + e] * g;
            else if (r < 144)  c = g_ct[(r - 16) * DD + e] * g;
            else if (r < 272)  c = g_cf[(r - 144) * DD + e] * g;
            else if (r == 272) c = ln_b[e];
            else               c = 0.f;
            vp[j] = c;
        }
        cg[e] = v;
    }
    __syncthreads();

    float a0 = 0.f, a1 = 0.f, a2 = 0.f, a3 = 0.f;
    #pragma unroll 4
    for (int k = 0; k < DD; k++) {
        float w = W1[k * E2 + e];
        float4 v = cg[k];
        a0 = fmaf(v.x, w, a0);
        a1 = fmaf(v.y, w, a1);
        a2 = fmaf(v.z, w, a2);
        a3 = fmaf(v.w, w, a3);
    }
    float acc[4] = {a0, a1, a2, a3};
    #pragma unroll
    for (int j = 0; j < 4; j++) {
        int r = r0 + j;
        if (r < 16)        g_ux[r * E2 + e] = acc[j];
        else if (r < 144)  g_ut[(r - 16) * E2 + e] = acc[j];
        else if (r < 272)  g_uf[(r - 144) * E2 + e] = acc[j];
        else if (r == 272) g_c[e] = acc[j] + b1[e];
    }
}

// ---------------- main: 16 combos/thread (4f x 4bn), e split 8 ways --------
// grid (t=128, fb=8); block 128 = 8 e-slices (eq) x 16 combo groups (cg).
// cg: fg = cg&3 -> f in {f0+fg+4*fi}, bng = cg>>2 -> bn in {bng+4*bi}.
__global__ void __launch_bounds__(128, 3)
k_main(const float* __restrict__ W2, const float* __restrict__ b2,
       float* __restrict__ out) {
    extern __shared__ float sm[];
    float* s_tf = sm;                  // [16][SROW]: ut[t] + uf[f0+r]
    float* s_ux = sm + 16 * SROW;      // [16][SROW]
    float* s_c  = sm + 32 * SROW;      // [512]
    float* s_w0 = s_c + E2;            // [512]
    float* s_w1 = s_w0 + E2;           // [512]

    int t   = blockIdx.x;
    int f0  = blockIdx.y * 16;
    int tid = threadIdx.x;

    // fill smem: thread owns float4 column e4 = tid, loops 16 rows
    {
        const float4* ut4 = (const float4*)(g_ut + t * E2);
        float4 a = ut4[tid];
        #pragma unroll 4
        for (int r = 0; r < 16; r++) {
            float4 b = ((const float4*)(g_uf + (f0 + r) * E2))[tid];
            ((float4*)(s_tf + r * SROW))[tid] =
                make_float4(a.x + b.x, a.y + b.y, a.z + b.z, a.w + b.w);
            ((float4*)(s_ux + r * SROW))[tid] = ((const float4*)(g_ux + r * E2))[tid];
        }
        for (int i = tid; i < E2; i += 128) {
            s_c[i]  = g_c[i];
            s_w0[i] = W2[2 * i];
            s_w1[i] = W2[2 * i + 1];
        }
    }

    int eq  = tid >> 4;     // e-slice 0..7 (64 floats each)
    int cg  = tid & 15;     // combo group
    int fg  = cg & 3;       // f = f0 + fg + 4*fi
    int bng = cg >> 2;      // bn = bng + 4*bi

    // per-combo rinv (packed), from decomposed variance terms
    u64 rinv2[16];
    float qt = g_qt[t];
    #pragma unroll
    for (int fi = 0; fi < 4; fi++) {
        int f = f0 + fg + 4 * fi;
        float qtf = qt + g_qf[f] + 2.0f * g_dtf[t * 128 + f];
        #pragma unroll
        for (int bi = 0; bi < 4; bi++) {
            int bn = bng + 4 * bi;
            float var = (qtf + g_qx[bn]
                         + 2.0f * (g_dxt[bn * 128 + t] + g_dxf[bn * 128 + f]))
                        * (1.0f / 256.0f);
            rinv2[fi * 4 + bi] = pack2(rsqrtf(var + EPS));
        }
    }
    __syncthreads();

    const ulonglong2* ptf[4];
    const ulonglong2* pux[4];
    #pragma unroll
    for (int x = 0; x < 4; x++) {
        ptf[x] = (const ulonglong2*)(s_tf + (fg + 4 * x) * SROW) + eq * 16;
        pux[x] = (const ulonglong2*)(s_ux + (bng + 4 * x) * SROW) + eq * 16;
    }
    const ulonglong2* pc  = (const ulonglong2*)s_c  + eq * 16;
    const ulonglong2* pw0 = (const ulonglong2*)s_w0 + eq * 16;
    const ulonglong2* pw1 = (const ulonglong2*)s_w1 + eq * 16;

    u64 a0[16], a1[16];
    #pragma unroll
    for (int k = 0; k < 16; k++) { a0[k] = 0ull; a1[k] = 0ull; }

    #pragma unroll 1
    for (int i = 0; i < 16; i++) {
        ulonglong2 TF[4], UX[4];
        #pragma unroll
        for (int x = 0; x < 4; x++) { TF[x] = ptf[x][i]; UX[x] = pux[x][i]; }
        ulonglong2 C = pc[i], V0 = pw0[i], V1 = pw1[i];

        #pragma unroll
        for (int fi = 0; fi < 4; fi++) {
            #pragma unroll
            for (int bi = 0; bi < 4; bi++) {
                int k = fi * 4 + bi;
                u64 z0 = relu2(fma2(rinv2[k], add2(TF[fi].x, UX[bi].x), C.x));
                u64 z1 = relu2(fma2(rinv2[k], add2(TF[fi].y, UX[bi].y), C.y));
                a0[k] = fma2(z0, V0.x, a0[k]);
                a0[k] = fma2(z1, V0.y, a0[k]);
                a1[k] = fma2(z0, V1.x, a1[k]);
                a1[k] = fma2(z1, V1.y, a1[k]);
            }
        }
    }

    // merge 8 e-slice partials via smem, then store
    __syncthreads();                   // all smem-stream reads done
    float* mrg = sm;                   // [(pair)*2 + o][eq] = 4096 floats
    #pragma unroll
    for (int k = 0; k < 16; k++) {
        int pair = k * 16 + cg;
        mrg[(pair * 2 + 0) * 8 + eq] = sum2(a0[k]);
        mrg[(pair * 2 + 1) * 8 + eq] = sum2(a1[k]);
    }
    __syncthreads();

    float b20 = b2[0], b21 = b2[1];
    #pragma unroll
    for (int j = 0; j < 2; j++) {
        int p = tid * 2 + j;           // pair id 0..255
        float o0 = b20, o1 = b21;
        const float4* m4 = (const float4*)(mrg + p * 16);
        #pragma unroll
        for (int q = 0; q < 2; q++) {
            float4 v0 = m4[q];         // o=0 partials
            float4 v1 = m4[q + 2];     // o=1 partials
            o0 += v0.x + v0.y + v0.z + v0.w;
            o1 += v1.x + v1.y + v1.z + v1.w;
        }
        int k  = p >> 4, c2 = p & 15;
        int f  = f0 + (c2 & 3) + 4 * (k >> 2);
        int bn = (c2 >> 2) + 4 * (k & 3);
        ((float2*)out)[(bn * NT + t) * NF + f] = make_float2(o0, o1);
    }
}

// ---------------- launch ----------------------------------------------------
extern "C" void kernel_launch(void* const* d_in, const int* in_sizes, int n_in,
                              void* d_out, int out_size) {
    const float* x     = (const float*)d_in[0];
    const float* t_emb = (const float*)d_in[1];
    const float* f_emb = (const float*)d_in[2];
    const float* ln_g  = (const float*)d_in[3];
    const float* ln_b  = (const float*)d_in[4];
    const float* W1    = (const float*)d_in[5];
    const float* b1    = (const float*)d_in[6];
    const float* W2    = (const float*)d_in[7];
    const float* b2    = (const float*)d_in[8];
    float* out = (float*)d_out;

    const int smem_bytes = (32 * SROW + 3 * E2) * (int)sizeof(float);  // 72192
    cudaFuncSetAttribute(k_main, cudaFuncAttributeMaxDynamicSharedMemorySize, smem_bytes);

    k_center<<<272, 256>>>(x, t_emb, f_emb);
    k_dots<<<2560, 256>>>();
    k_project<<<69, 512>>>(ln_g, ln_b, W1, b1);
    dim3 grid(NT, 8);
    k_main<<<grid, 128, smem_bytes>>>(W2, b2, out);
}

// round 5
// speedup vs baseline: 1.0728x; 1.0728x over previous
#include <cuda_runtime.h>

#define DD   256
#define E2   512
#define NT   128
#define NF   128
#define NBN  16
#define SROW 516
#define EPS  1e-5f

typedef unsigned long long u64;

// ---------------- packed f32x2 helpers (Blackwell 2xFP32) ------------------
__device__ __forceinline__ u64 add2(u64 a, u64 b) {
    u64 d; asm("add.rn.f32x2 %0,%1,%2;" : "=l"(d) : "l"(a), "l"(b)); return d;
}
__device__ __forceinline__ u64 fma2(u64 a, u64 b, u64 c) {
    u64 d; asm("fma.rn.f32x2 %0,%1,%2,%3;" : "=l"(d) : "l"(a), "l"(b), "l"(c)); return d;
}
__device__ __forceinline__ u64 relu2(u64 a) {
    u64 d;
    asm("{\n\t.reg .f32 l,h;\n\tmov.b64 {l,h}, %1;\n\t"
        "max.f32 l, l, 0f00000000;\n\tmax.f32 h, h, 0f00000000;\n\t"
        "mov.b64 %0, {l,h};\n\t}" : "=l"(d) : "l"(a));
    return d;
}
__device__ __forceinline__ float sum2(u64 a) {
    float l, h; asm("mov.b64 {%0,%1}, %2;" : "=f"(l), "=f"(h) : "l"(a)); return l + h;
}
__device__ __forceinline__ u64 pack2(float v) {
    u64 d; asm("mov.b64 %0, {%1,%1};" : "=l"(d) : "f"(v)); return d;
}

// ---------------- scratch (device globals; no allocation allowed) ----------
__device__ float g_cx[NBN * DD];
__device__ float g_ct[NT * DD];
__device__ float g_cf[NF * DD];
__device__ float g_qx[NBN];
__device__ float g_qt[NT];
__device__ float g_qf[NF];
__device__ float g_dxt[NBN * NT];
__device__ float g_dxf[NBN * NF];
__device__ float g_dtf[NT * NF];
__device__ float g_ux[NBN * E2];
__device__ float g_ut[NT * E2];
__device__ float g_uf[NF * E2];
__device__ float g_c[E2];

// ---------------- P1: center each embedding row, store centered + sq-norm --
__global__ void k_center(const float* __restrict__ x,
                         const float* __restrict__ t_emb,
                         const float* __restrict__ f_emb) {
    __shared__ float red[8];
    __shared__ float s_mu;
    int r = blockIdx.x;
    const float* src;
    float* dst;
    float* q;
    if (r < 16)       { src = x + r * DD;            dst = g_cx + r * DD;        q = g_qx + r; }
    else if (r < 144) { int i = r - 16;  src = t_emb + i * DD; dst = g_ct + i * DD; q = g_qt + i; }
    else              { int i = r - 144; src = f_emb + i * DD; dst = g_cf + i * DD; q = g_qf + i; }

    int tid = threadIdx.x;
    float v = src[tid];

    float s = v;
    #pragma unroll
    for (int o = 16; o; o >>= 1) s += __shfl_xor_sync(0xffffffffu, s, o);
    if ((tid & 31) == 0) red[tid >> 5] = s;
    __syncthreads();
    if (tid == 0) {
        float tot = 0.f;
        #pragma unroll
        for (int i = 0; i < 8; i++) tot += red[i];
        s_mu = tot * (1.0f / DD);
    }
    __syncthreads();

    float c = v - s_mu;
    dst[tid] = c;

    s = c * c;
    #pragma unroll
    for (int o = 16; o; o >>= 1) s += __shfl_xor_sync(0xffffffffu, s, o);
    __syncthreads();
    if ((tid & 31) == 0) red[tid >> 5] = s;
    __syncthreads();
    if (tid == 0) {
        float tot = 0.f;
        #pragma unroll
        for (int i = 0; i < 8; i++) tot += red[i];
        *q = tot;
    }
}

// ---------------- P2: pairwise dot products (one warp per dot) -------------
__global__ void k_dots() {
    int w    = (blockIdx.x * blockDim.x + threadIdx.x) >> 5;
    int lane = threadIdx.x & 31;
    const float *a, *b;
    float* dst;
    if (w < 2048) {
        int i = w >> 7, j = w & 127;
        a = g_cx + i * DD; b = g_ct + j * DD; dst = g_dxt + w;
    } else if (w < 4096) {
        int w2 = w - 2048;
        int i = w2 >> 7, j = w2 & 127;
        a = g_cx + i * DD; b = g_cf + j * DD; dst = g_dxf + w2;
    } else {
        int w3 = w - 4096;
        a = g_ct + (w3 >> 7) * DD; b = g_cf + (w3 & 127) * DD; dst = g_dtf + w3;
    }
    const float4* a4 = (const float4*)a;
    const float4* b4 = (const float4*)b;
    float s = 0.f;
    #pragma unroll
    for (int j = 0; j < 2; j++) {
        float4 av = a4[lane * 2 + j];
        float4 bv = b4[lane * 2 + j];
        s += av.x * bv.x + av.y * bv.y + av.z * bv.z + av.w * bv.w;
    }
    #pragma unroll
    for (int o = 16; o; o >>= 1) s += __shfl_xor_sync(0xffffffffu, s, o);
    if (lane == 0) *dst = s;
}

// ---------------- P3: 4 rows/block through W1 (one W1 stream per block) ----
__global__ void k_project(const float* __restrict__ ln_g,
                          const float* __restrict__ ln_b,
                          const float* __restrict__ W1,
                          const float* __restrict__ b1) {
    __shared__ float4 cg[DD];   // [k] -> (row0..row3)
    int r0 = blockIdx.x * 4;
    int e = threadIdx.x;        // 512 threads

    if (e < DD) {
        float g = ln_g[e];
        float4 v;
        float* vp = (float*)&v;
        #pragma unroll
        for (int j = 0; j < 4; j++) {
            int r = r0 + j;
            float c;
            if (r < 16)        c = g_cx[r * DD + e] * g;
            else if (r < 144)  c = g_ct[(r - 16) * DD + e] * g;
            else if (r < 272)  c = g_cf[(r - 144) * DD + e] * g;
            else if (r == 272) c = ln_b[e];
            else               c = 0.f;
            vp[j] = c;
        }
        cg[e] = v;
    }
    __syncthreads();

    float a0 = 0.f, a1 = 0.f, a2 = 0.f, a3 = 0.f;
    #pragma unroll 4
    for (int k = 0; k < DD; k++) {
        float w = W1[k * E2 + e];
        float4 v = cg[k];
        a0 = fmaf(v.x, w, a0);
        a1 = fmaf(v.y, w, a1);
        a2 = fmaf(v.z, w, a2);
        a3 = fmaf(v.w, w, a3);
    }
    float acc[4] = {a0, a1, a2, a3};
    #pragma unroll
    for (int j = 0; j < 4; j++) {
        int r = r0 + j;
        if (r < 16)        g_ux[r * E2 + e] = acc[j];
        else if (r < 144)  g_ut[(r - 16) * E2 + e] = acc[j];
        else if (r < 272)  g_uf[(r - 144) * E2 + e] = acc[j];
        else if (r == 272) g_c[e] = acc[j] + b1[e];
    }
}

// ---------------- main: 8 combos/thread (4f x 2bn), 256 thr, 8 e-slices ----
// grid (t=128, fb=8); block 256 = 8 e-slices (eq, warp-uniform) x 32 lanes.
// lane: fg = lane&3 -> f = f0 + fg + 4*fi (fi 0..3);
//       bng = lane>>2 -> bn = bng + 8*bi (bi 0..1).
__global__ void __launch_bounds__(256, 2)
k_main(const float* __restrict__ W2, const float* __restrict__ b2,
       float* __restrict__ out) {
    extern __shared__ float sm[];
    float* s_tf = sm;                  // [16][SROW]: ut[t] + uf[f0+r]
    float* s_ux = sm + 16 * SROW;      // [16][SROW]
    float* s_c  = sm + 32 * SROW;      // [512]
    float* s_w0 = s_c + E2;            // [512]
    float* s_w1 = s_w0 + E2;           // [512]

    int t   = blockIdx.x;
    int f0  = blockIdx.y * 16;
    int tid = threadIdx.x;

    // fill smem: 256 threads = 2 halves x 128 float4 columns
    {
        int half = tid >> 7;           // rows [8*half, 8*half+8)
        int e4   = tid & 127;
        const float4* ut4 = (const float4*)(g_ut + t * E2);
        float4 a = ut4[e4];
        #pragma unroll 4
        for (int r = half * 8; r < half * 8 + 8; r++) {
            float4 b = ((const float4*)(g_uf + (f0 + r) * E2))[e4];
            ((float4*)(s_tf + r * SROW))[e4] =
                make_float4(a.x + b.x, a.y + b.y, a.z + b.z, a.w + b.w);
            ((float4*)(s_ux + r * SROW))[e4] = ((const float4*)(g_ux + r * E2))[e4];
        }
        for (int i = tid; i < E2; i += 256) {
            s_c[i]  = g_c[i];
            s_w0[i] = W2[2 * i];
            s_w1[i] = W2[2 * i + 1];
        }
    }

    int eq   = tid >> 5;    // e-slice 0..7 (warp-uniform)
    int lane = tid & 31;
    int fg   = lane & 3;    // f = f0 + fg + 4*fi
    int bng  = lane >> 2;   // bn = bng + 8*bi

    // per-combo rinv (packed), from decomposed variance terms
    u64 rinv2[8];
    float qt = g_qt[t];
    #pragma unroll
    for (int fi = 0; fi < 4; fi++) {
        int f = f0 + fg + 4 * fi;
        float qtf = qt + g_qf[f] + 2.0f * g_dtf[t * 128 + f];
        #pragma unroll
        for (int bi = 0; bi < 2; bi++) {
            int bn = bng + 8 * bi;
            float var = (qtf + g_qx[bn]
                         + 2.0f * (g_dxt[bn * 128 + t] + g_dxf[bn * 128 + f]))
                        * (1.0f / 256.0f);
            rinv2[fi * 2 + bi] = pack2(rsqrtf(var + EPS));
        }
    }
    __syncthreads();

    const ulonglong2* ptf[4];
    #pragma unroll
    for (int fi = 0; fi < 4; fi++)
        ptf[fi] = (const ulonglong2*)(s_tf + (fg + 4 * fi) * SROW) + eq * 16;
    const ulonglong2* pux0 = (const ulonglong2*)(s_ux + bng * SROW) + eq * 16;
    const ulonglong2* pux1 = (const ulonglong2*)(s_ux + (bng + 8) * SROW) + eq * 16;
    const ulonglong2* pc  = (const ulonglong2*)s_c  + eq * 16;
    const ulonglong2* pw0 = (const ulonglong2*)s_w0 + eq * 16;
    const ulonglong2* pw1 = (const ulonglong2*)s_w1 + eq * 16;

    u64 A0[8], A1[8];
    #pragma unroll
    for (int k = 0; k < 8; k++) { A0[k] = 0ull; A1[k] = 0ull; }

    #pragma unroll 2
    for (int i = 0; i < 16; i++) {
        ulonglong2 TF[4];
        #pragma unroll
        for (int x = 0; x < 4; x++) TF[x] = ptf[x][i];
        ulonglong2 UX0 = pux0[i], UX1 = pux1[i];
        ulonglong2 C = pc[i], V0 = pw0[i], V1 = pw1[i];

        #pragma unroll
        for (int fi = 0; fi < 4; fi++) {
            #pragma unroll
            for (int bi = 0; bi < 2; bi++) {
                ulonglong2 UX = bi ? UX1 : UX0;
                int k = fi * 2 + bi;
                u64 z0 = relu2(fma2(rinv2[k], add2(TF[fi].x, UX.x), C.x));
                u64 z1 = relu2(fma2(rinv2[k], add2(TF[fi].y, UX.y), C.y));
                A0[k] = fma2(z0, V0.x, A0[k]);
                A0[k] = fma2(z1, V0.y, A0[k]);
                A1[k] = fma2(z0, V1.x, A1[k]);
                A1[k] = fma2(z1, V1.y, A1[k]);
            }
        }
    }

    // merge 8 e-slice partials via smem (stride 9 to break bank collisions)
    __syncthreads();                   // all smem-stream reads done
    float* mrg = sm;                   // [(kg*2+o)*9 + eq], 512*9 = 4608 floats
    #pragma unroll
    for (int k = 0; k < 8; k++) {
        int fi = k >> 1, bi = k & 1;
        int kg = (fg + 4 * fi) * 16 + (bng + 8 * bi);   // combo id 0..255
        mrg[(kg * 2 + 0) * 9 + eq] = sum2(A0[k]);
        mrg[(kg * 2 + 1) * 9 + eq] = sum2(A1[k]);
    }
    __syncthreads();

    // thread tid reduces combo kg = tid
    {
        float o0 = b2[0], o1 = b2[1];
        int base = tid * 18;
        #pragma unroll
        for (int q = 0; q < 8; q++) {
            o0 += mrg[base + q];
            o1 += mrg[base + 9 + q];
        }
        int f  = f0 + (tid >> 4);
        int bn = tid & 15;
        ((float2*)out)[(bn * NT + t) * NF + f] = make_float2(o0, o1);
    }
}

// ---------------- launch ----------------------------------------------------
extern "C" void kernel_launch(void* const* d_in, const int* in_sizes, int n_in,
                              void* d_out, int out_size) {
    const float* x     = (const float*)d_in[0];
    const float* t_emb = (const float*)d_in[1];
    const float* f_emb = (const float*)d_in[2];
    const float* ln_g  = (const float*)d_in[3];
    const float* ln_b  = (const float*)d_in[4];
    const float* W1    = (const float*)d_in[5];
    const float* b1    = (const float*)d_in[6];
    const float* W2    = (const float*)d_in[7];
    const float* b2    = (const float*)d_in[8];
    float* out = (float*)d_out;

    const int smem_bytes = (32 * SROW + 3 * E2) * (int)sizeof(float);  // 72192
    cudaFuncSetAttribute(k_main, cudaFuncAttributeMaxDynamicSharedMemorySize, smem_bytes);

    k_center<<<272, 256>>>(x, t_emb, f_emb);
    k_dots<<<2560, 256>>>();
    k_project<<<69, 512>>>(ln_g, ln_b, W1, b1);
    dim3 grid(NT, 8);
    k_main<<<grid, 256, smem_bytes>>>(W2, b2, out);
}

// round 7
// speedup vs baseline: 1.0734x; 1.0006x over previous
#include <cuda_runtime.h>

#define DD   256
#define E2   512
#define NT   128
#define NF   128
#define NBN  16
#define SROW 516
#define EPS  1e-5f

typedef unsigned long long u64;

// ---------------- packed f32x2 helpers (Blackwell 2xFP32) ------------------
__device__ __forceinline__ u64 add2(u64 a, u64 b) {
    u64 d; asm("add.rn.f32x2 %0,%1,%2;" : "=l"(d) : "l"(a), "l"(b)); return d;
}
__device__ __forceinline__ u64 fma2(u64 a, u64 b, u64 c) {
    u64 d; asm("fma.rn.f32x2 %0,%1,%2,%3;" : "=l"(d) : "l"(a), "l"(b), "l"(c)); return d;
}
__device__ __forceinline__ u64 relu2(u64 a) {
    u64 d;
    asm("{\n\t.reg .f32 l,h;\n\tmov.b64 {l,h}, %1;\n\t"
        "max.f32 l, l, 0f00000000;\n\tmax.f32 h, h, 0f00000000;\n\t"
        "mov.b64 %0, {l,h};\n\t}" : "=l"(d) : "l"(a));
    return d;
}
__device__ __forceinline__ float sum2(u64 a) {
    float l, h; asm("mov.b64 {%0,%1}, %2;" : "=f"(l), "=f"(h) : "l"(a)); return l + h;
}
__device__ __forceinline__ u64 pack2(float v) {
    u64 d; asm("mov.b64 %0, {%1,%1};" : "=l"(d) : "f"(v)); return d;
}

// ---------------- scratch (device globals; no allocation allowed) ----------
__device__ float g_cx[NBN * DD];
__device__ float g_ct[NT * DD];
__device__ float g_cf[NF * DD];
__device__ float g_qx[NBN];
__device__ float g_qt[NT];
__device__ float g_qf[NF];
__device__ float g_dxt[NBN * NT];
__device__ float g_dxf[NBN * NF];
__device__ float g_dtf[NT * NF];
__device__ float g_ux[NBN * E2];
__device__ float g_ut[NT * E2];
__device__ float g_uf[NF * E2];
__device__ float g_c[E2];

// ---------------- P1: center each embedding row, store centered + sq-norm --
__global__ void k_center(const float* __restrict__ x,
                         const float* __restrict__ t_emb,
                         const float* __restrict__ f_emb) {
    __shared__ float red[8];
    __shared__ float s_mu;
    int r = blockIdx.x;
    const float* src;
    float* dst;
    float* q;
    if (r < 16)       { src = x + r * DD;            dst = g_cx + r * DD;        q = g_qx + r; }
    else if (r < 144) { int i = r - 16;  src = t_emb + i * DD; dst = g_ct + i * DD; q = g_qt + i; }
    else              { int i = r - 144; src = f_emb + i * DD; dst = g_cf + i * DD; q = g_qf + i; }

    int tid = threadIdx.x;
    float v = src[tid];

    float s = v;
    #pragma unroll
    for (int o = 16; o; o >>= 1) s += __shfl_xor_sync(0xffffffffu, s, o);
    if ((tid & 31) == 0) red[tid >> 5] = s;
    __syncthreads();
    if (tid == 0) {
        float tot = 0.f;
        #pragma unroll
        for (int i = 0; i < 8; i++) tot += red[i];
        s_mu = tot * (1.0f / DD);
    }
    __syncthreads();

    float c = v - s_mu;
    dst[tid] = c;

    s = c * c;
    #pragma unroll
    for (int o = 16; o; o >>= 1) s += __shfl_xor_sync(0xffffffffu, s, o);
    __syncthreads();
    if ((tid & 31) == 0) red[tid >> 5] = s;
    __syncthreads();
    if (tid == 0) {
        float tot = 0.f;
        #pragma unroll
        for (int i = 0; i < 8; i++) tot += red[i];
        *q = tot;
    }
}

// ---------------- P2: pairwise dot products (one warp per dot) -------------
__global__ void k_dots() {
    int w    = (blockIdx.x * blockDim.x + threadIdx.x) >> 5;
    int lane = threadIdx.x & 31;
    const float *a, *b;
    float* dst;
    if (w < 2048) {
        int i = w >> 7, j = w & 127;
        a = g_cx + i * DD; b = g_ct + j * DD; dst = g_dxt + w;
    } else if (w < 4096) {
        int w2 = w - 2048;
        int i = w2 >> 7, j = w2 & 127;
        a = g_cx + i * DD; b = g_cf + j * DD; dst = g_dxf + w2;
    } else {
        int w3 = w - 4096;
        a = g_ct + (w3 >> 7) * DD; b = g_cf + (w3 & 127) * DD; dst = g_dtf + w3;
    }
    const float4* a4 = (const float4*)a;
    const float4* b4 = (const float4*)b;
    float s = 0.f;
    #pragma unroll
    for (int j = 0; j < 2; j++) {
        float4 av = a4[lane * 2 + j];
        float4 bv = b4[lane * 2 + j];
        s += av.x * bv.x + av.y * bv.y + av.z * bv.z + av.w * bv.w;
    }
    #pragma unroll
    for (int o = 16; o; o >>= 1) s += __shfl_xor_sync(0xffffffffu, s, o);
    if (lane == 0) *dst = s;
}

// ---------------- P3: 4 rows/block through W1 (one W1 stream per block) ----
__global__ void k_project(const float* __restrict__ ln_g,
                          const float* __restrict__ ln_b,
                          const float* __restrict__ W1,
                          const float* __restrict__ b1) {
    __shared__ float4 cg[DD];   // [k] -> (row0..row3)
    int r0 = blockIdx.x * 4;
    int e = threadIdx.x;        // 512 threads

    if (e < DD) {
        float g = ln_g[e];
        float4 v;
        float* vp = (float*)&v;
        #pragma unroll
        for (int j = 0; j < 4; j++) {
            int r = r0 + j;
            float c;
            if (r < 16)        c = g_cx[r * DD + e] * g;
            else if (r < 144)  c = g_ct[(r - 16) * DD + e] * g;
            else if (r < 272)  c = g_cf[(r - 144) * DD + e] * g;
            else if (r == 272) c = ln_b[e];
            else               c = 0.f;
            vp[j] = c;
        }
        cg[e] = v;
    }
    __syncthreads();

    float a0 = 0.f, a1 = 0.f, a2 = 0.f, a3 = 0.f;
    #pragma unroll 4
    for (int k = 0; k < DD; k++) {
        float w = W1[k * E2 + e];
        float4 v = cg[k];
        a0 = fmaf(v.x, w, a0);
        a1 = fmaf(v.y, w, a1);
        a2 = fmaf(v.z, w, a2);
        a3 = fmaf(v.w, w, a3);
    }
    float acc[4] = {a0, a1, a2, a3};
    #pragma unroll
    for (int j = 0; j < 4; j++) {
        int r = r0 + j;
        if (r < 16)        g_ux[r * E2 + e] = acc[j];
        else if (r < 144)  g_ut[(r - 16) * E2 + e] = acc[j];
        else if (r < 272)  g_uf[(r - 144) * E2 + e] = acc[j];
        else if (r == 272) g_c[e] = acc[j] + b1[e];
    }
}

// ---------------- main: 8 combos/thread (4f x 2bn), 256 thr, 3 CTAs/SM -----
// grid (t=128, fb=8); block 256 = 8 e-slices (eq, warp-uniform) x 32 lanes.
// lane: fg = lane&3 -> f = f0 + fg + 4*fi (fi 0..3);
//       bng = lane>>2 -> bn = bng + 8*bi (bi 0..1).
// Offsets in ulonglong2 units: 1 smem row = SROW floats = 129 ull2.
//   TF row stride (4 rows)  = 516 ull2
//   UX row stride (8 rows)  = 1032 ull2
__global__ void __launch_bounds__(256, 3)
k_main(const float* __restrict__ W2, const float* __restrict__ b2,
       float* __restrict__ out) {
    extern __shared__ float sm[];
    float* s_tf = sm;                  // [16][SROW]: ut[t] + uf[f0+r]
    float* s_ux = sm + 16 * SROW;      // [16][SROW]
    float* s_c  = sm + 32 * SROW;      // [512] then w0[512], w1[512]

    int t   = blockIdx.x;
    int f0  = blockIdx.y * 16;
    int tid = threadIdx.x;

    // fill smem: 256 threads = 2 halves x 128 float4 columns
    {
        int half = tid >> 7;           // rows [8*half, 8*half+8)
        int e4   = tid & 127;
        const float4* ut4 = (const float4*)(g_ut + t * E2);
        float4 a = ut4[e4];
        #pragma unroll 4
        for (int r = half * 8; r < half * 8 + 8; r++) {
            float4 b = ((const float4*)(g_uf + (f0 + r) * E2))[e4];
            ((float4*)(s_tf + r * SROW))[e4] =
                make_float4(a.x + b.x, a.y + b.y, a.z + b.z, a.w + b.w);
            ((float4*)(s_ux + r * SROW))[e4] = ((const float4*)(g_ux + r * E2))[e4];
        }
        for (int i = tid; i < E2; i += 256) {
            s_c[i]          = g_c[i];
            s_c[E2 + i]     = W2[2 * i];        // w0
            s_c[2 * E2 + i] = W2[2 * i + 1];    // w1
        }
    }

    int eq   = tid >> 5;    // e-slice 0..7 (warp-uniform)
    int lane = tid & 31;
    int fg   = lane & 3;    // f = f0 + fg + 4*fi
    int bng  = lane >> 2;   // bn = bng + 8*bi

    // per-combo rinv (packed), from decomposed variance terms
    u64 rinv2[8];
    float qt = g_qt[t];
    #pragma unroll
    for (int fi = 0; fi < 4; fi++) {
        int f = f0 + fg + 4 * fi;
        float qtf = qt + g_qf[f] + 2.0f * g_dtf[t * 128 + f];
        #pragma unroll
        for (int bi = 0; bi < 2; bi++) {
            int bn = bng + 8 * bi;
            float var = (qtf + g_qx[bn]
                         + 2.0f * (g_dxt[bn * 128 + t] + g_dxf[bn * 128 + f]))
                        * (1.0f / 256.0f);
            rinv2[fi * 2 + bi] = pack2(rsqrtf(var + EPS));
        }
    }
    __syncthreads();

    // single base pointers; row strides become constant ull2 offsets
    const ulonglong2* ptf = (const ulonglong2*)(s_tf + fg * SROW) + eq * 16;   // +fi*516
    const ulonglong2* pux = (const ulonglong2*)(s_ux + bng * SROW) + eq * 16;  // +bi*1032
    const ulonglong2* pcv = (const ulonglong2*)s_c + eq * 16;                  // c, +128 w0, +256 w1

    u64 A0[8], A1[8];
    #pragma unroll
    for (int k = 0; k < 8; k++) { A0[k] = 0ull; A1[k] = 0ull; }

    #pragma unroll 2
    for (int i = 0; i < 16; i++) {
        ulonglong2 C   = pcv[i];
        ulonglong2 V0  = pcv[i + 128];
        ulonglong2 V1  = pcv[i + 256];
        ulonglong2 UX0 = pux[i];
        ulonglong2 UX1 = pux[i + 1032];       // +8 rows
        ulonglong2 TFa = ptf[i];              // fi = 0
        ulonglong2 TFb = ptf[i + 516];        // fi = 1

        // phase A: fi = 0, 1
        #pragma unroll
        for (int fi = 0; fi < 2; fi++) {
            ulonglong2 TF = fi ? TFb : TFa;
            #pragma unroll
            for (int bi = 0; bi < 2; bi++) {
                ulonglong2 UX = bi ? UX1 : UX0;
                int k = fi * 2 + bi;
                u64 z0 = relu2(fma2(rinv2[k], add2(TF.x, UX.x), C.x));
                u64 z1 = relu2(fma2(rinv2[k], add2(TF.y, UX.y), C.y));
                A0[k] = fma2(z0, V0.x, A0[k]);
                A0[k] = fma2(z1, V0.y, A0[k]);
                A1[k] = fma2(z0, V1.x, A1[k]);
                A1[k] = fma2(z1, V1.y, A1[k]);
            }
        }

        // phase B: fi = 2, 3 (reload TF, everything else still live)
        TFa = ptf[i + 1032];                  // fi = 2
        TFb = ptf[i + 1548];                  // fi = 3
        #pragma unroll
        for (int fi = 2; fi < 4; fi++) {
            ulonglong2 TF = (fi == 3) ? TFb : TFa;
            #pragma unroll
            for (int bi = 0; bi < 2; bi++) {
                ulonglong2 UX = bi ? UX1 : UX0;
                int k = fi * 2 + bi;
                u64 z0 = relu2(fma2(rinv2[k], add2(TF.x, UX.x), C.x));
                u64 z1 = relu2(fma2(rinv2[k], add2(TF.y, UX.y), C.y));
                A0[k] = fma2(z0, V0.x, A0[k]);
                A0[k] = fma2(z1, V0.y, A0[k]);
                A1[k] = fma2(z0, V1.x, A1[k]);
                A1[k] = fma2(z1, V1.y, A1[k]);
            }
        }
    }

    // merge 8 e-slice partials via smem (stride 9 to break bank collisions)
    __syncthreads();                   // all smem-stream reads done
    float* mrg = sm;                   // [(kg*2+o)*9 + eq], 512*9 = 4608 floats
    #pragma unroll
    for (int k = 0; k < 8; k++) {
        int fi = k >> 1, bi = k & 1;
        int kg = (fg + 4 * fi) * 16 + (bng + 8 * bi);   // combo id 0..255
        mrg[(kg * 2 + 0) * 9 + eq] = sum2(A0[k]);
        mrg[(kg * 2 + 1) * 9 + eq] = sum2(A1[k]);
    }
    __syncthreads();

    // thread tid reduces combo kg = tid
    {
        float o0 = b2[0], o1 = b2[1];
        int base = tid * 18;
        #pragma unroll
        for (int q = 0; q < 8; q++) {
            o0 += mrg[base + q];
            o1 += mrg[base + 9 + q];
        }
        int f  = f0 + (tid >> 4);
        int bn = tid & 15;
        ((float2*)out)[(bn * NT + t) * NF + f] = make_float2(o0, o1);
    }
}

// ---------------- launch ----------------------------------------------------
extern "C" void kernel_launch(void* const* d_in, const int* in_sizes, int n_in,
                              void* d_out, int out_size) {
    const float* x     = (const float*)d_in[0];
    const float* t_emb = (const float*)d_in[1];
    const float* f_emb = (const float*)d_in[2];
    const float* ln_g  = (const float*)d_in[3];
    const float* ln_b  = (const float*)d_in[4];
    const float* W1    = (const float*)d_in[5];
    const float* b1    = (const float*)d_in[6];
    const float* W2    = (const float*)d_in[7];
    const float* b2    = (const float*)d_in[8];
    float* out = (float*)d_out;

    const int smem_bytes = (32 * SROW + 3 * E2) * (int)sizeof(float);  // 72192
    cudaFuncSetAttribute(k_main, cudaFuncAttributeMaxDynamicSharedMemorySize, smem_bytes);

    k_center<<<272, 256>>>(x, t_emb, f_emb);
    k_dots<<<2560, 256>>>();
    k_project<<<69, 512>>>(ln_g, ln_b, W1, b1);
    dim3 grid(NT, 8);
    k_main<<<grid, 256, smem_bytes>>>(W2, b2, out);
}